// round 1
// baseline (speedup 1.0000x reference)
#include <cuda_runtime.h>
#include <cstdint>

// Problem constants
#define BATCH 8
#define SEQ   1024
#define EMB   768
#define NHEAD 12
#define HDIM  64
#define C3    (3*EMB)          // 2304
#define MROWS (BATCH*SEQ)      // 8192

// Scratch (module-load allocated, allowed by harness rules)
__device__ float g_qkv[(size_t)MROWS * C3];    // [8192, 2304]
__device__ float g_attn[(size_t)MROWS * EMB];  // [8192, 768]

// ---------------------------------------------------------------------------
// Tiled SGEMM with bias: C[M,N] = A[M,K] @ B[K,N] + bias[N]
// BM=BN=64, BK=16, 256 threads, 4x4 microtile per thread.
// Requires M%64==0, N%64==0, K%16==0 (true for all our shapes).
// ---------------------------------------------------------------------------
__global__ __launch_bounds__(256)
void sgemm_bias_kernel(const float* __restrict__ A,
                       const float* __restrict__ B,
                       const float* __restrict__ bias,
                       float* __restrict__ C,
                       int M, int N, int K)
{
    const int BM = 64, BN = 64, BK = 16;
    __shared__ float As[BK][BM];
    __shared__ float Bs[BK][BN];

    int tid = threadIdx.x;
    int tx = tid & 15;          // 0..15 -> N direction
    int ty = tid >> 4;          // 0..15 -> M direction
    int rowBase = blockIdx.y * BM;
    int colBase = blockIdx.x * BN;

    float acc[4][4];
#pragma unroll
    for (int i = 0; i < 4; i++)
#pragma unroll
        for (int j = 0; j < 4; j++) acc[i][j] = 0.f;

    for (int k0 = 0; k0 < K; k0 += BK) {
        // Load A tile (64 x 16) transposed into As[k][m]; one float4 per thread
        {
            int arow = tid >> 2;          // 0..63
            int kq   = tid & 3;           // 0..3  (k-quad)
            float4 av = *(const float4*)&A[(size_t)(rowBase + arow) * K + k0 + kq * 4];
            As[kq * 4 + 0][arow] = av.x;
            As[kq * 4 + 1][arow] = av.y;
            As[kq * 4 + 2][arow] = av.z;
            As[kq * 4 + 3][arow] = av.w;
        }
        // Load B tile (16 x 64); one float4 per thread
        {
            int brow = tid >> 4;          // 0..15
            int cq   = tid & 15;          // 0..15
            float4 bv = *(const float4*)&B[(size_t)(k0 + brow) * N + colBase + cq * 4];
            *(float4*)&Bs[brow][cq * 4] = bv;
        }
        __syncthreads();

#pragma unroll
        for (int k = 0; k < BK; k++) {
            float4 a = *(const float4*)&As[k][ty * 4];
            float4 b = *(const float4*)&Bs[k][tx * 4];
            float ar[4] = {a.x, a.y, a.z, a.w};
            float br[4] = {b.x, b.y, b.z, b.w};
#pragma unroll
            for (int i = 0; i < 4; i++)
#pragma unroll
                for (int j = 0; j < 4; j++)
                    acc[i][j] += ar[i] * br[j];
        }
        __syncthreads();
    }

    // Epilogue with bias
    float4 bia = *(const float4*)&bias[colBase + tx * 4];
    float br[4] = {bia.x, bia.y, bia.z, bia.w};
#pragma unroll
    for (int i = 0; i < 4; i++) {
        float4 o;
        o.x = acc[i][0] + br[0];
        o.y = acc[i][1] + br[1];
        o.z = acc[i][2] + br[2];
        o.w = acc[i][3] + br[3];
        *(float4*)&C[(size_t)(rowBase + ty * 4 + i) * N + colBase + tx * 4] = o;
    }
}

// ---------------------------------------------------------------------------
// Causal flash attention, fp32.
// Grid: (SEQ/128, BATCH*NHEAD). Block: 128 threads, 1 query row per thread.
// K/V streamed in 32-key tiles through shared memory; online softmax.
// qkv layout: [B*T, 3C] row-major; q at col h*64, k at C + h*64, v at 2C + h*64.
// Output written to g_attn [B*T, C] at col h*64.
// ---------------------------------------------------------------------------
__global__ __launch_bounds__(128)
void attn_kernel(const float* __restrict__ qkv, float* __restrict__ out)
{
    const int ROWS = 128, KT = 32;
    const float scale = 0.125f;   // 1/sqrt(64)

    int bh = blockIdx.y;
    int b  = bh / NHEAD;
    int h  = bh - b * NHEAD;
    int qbase = blockIdx.x * ROWS;
    int row = qbase + threadIdx.x;            // query index in [0, SEQ)

    __shared__ float Ks[KT][HDIM];
    __shared__ float Vs[KT][HDIM];

    // Load q row into registers
    float q[HDIM];
    {
        const float* qp = qkv + (size_t)(b * SEQ + row) * C3 + h * HDIM;
#pragma unroll
        for (int c4 = 0; c4 < 16; c4++) {
            float4 v = *(const float4*)(qp + c4 * 4);
            q[c4 * 4 + 0] = v.x; q[c4 * 4 + 1] = v.y;
            q[c4 * 4 + 2] = v.z; q[c4 * 4 + 3] = v.w;
        }
    }

    float o[HDIM];
#pragma unroll
    for (int c = 0; c < HDIM; c++) o[c] = 0.f;
    float m = -3.0e38f;
    float l = 0.f;

    int ntiles = (qbase + ROWS) / KT;   // keys needed: up to qbase+127

    for (int t = 0; t < ntiles; t++) {
        int kbase = t * KT;

        // Cooperative tile load: 32 keys x 64 floats for K and V (float4)
        for (int i = threadIdx.x; i < KT * 16; i += ROWS) {
            int r  = i >> 4;
            int cq = i & 15;
            size_t base = (size_t)(b * SEQ + kbase + r) * C3 + h * HDIM + cq * 4;
            *(float4*)&Ks[r][cq * 4] = *(const float4*)(qkv + base + EMB);
            *(float4*)&Vs[r][cq * 4] = *(const float4*)(qkv + base + 2 * EMB);
        }
        __syncthreads();

        if (kbase <= row) {
            // Scores for this tile
            float s[KT];
#pragma unroll 4
            for (int j = 0; j < KT; j++) {
                float a0 = 0.f, a1 = 0.f, a2 = 0.f, a3 = 0.f;
#pragma unroll
                for (int c4 = 0; c4 < 16; c4++) {
                    float4 kk = *(const float4*)&Ks[j][c4 * 4];
                    a0 += q[c4 * 4 + 0] * kk.x;
                    a1 += q[c4 * 4 + 1] * kk.y;
                    a2 += q[c4 * 4 + 2] * kk.z;
                    a3 += q[c4 * 4 + 3] * kk.w;
                }
                s[j] = (a0 + a1 + a2 + a3) * scale;
            }
            // Causal mask within tile
            if (kbase + KT - 1 > row) {
#pragma unroll
                for (int j = 0; j < KT; j++)
                    if (kbase + j > row) s[j] = -3.0e38f;
            }
            // Online softmax update
            float mt = m;
#pragma unroll
            for (int j = 0; j < KT; j++) mt = fmaxf(mt, s[j]);
            float corr = __expf(m - mt);
            l *= corr;
#pragma unroll
            for (int c = 0; c < HDIM; c++) o[c] *= corr;
#pragma unroll 4
            for (int j = 0; j < KT; j++) {
                float p = __expf(s[j] - mt);
                l += p;
#pragma unroll
                for (int c4 = 0; c4 < 16; c4++) {
                    float4 vv = *(const float4*)&Vs[j][c4 * 4];
                    o[c4 * 4 + 0] += p * vv.x;
                    o[c4 * 4 + 1] += p * vv.y;
                    o[c4 * 4 + 2] += p * vv.z;
                    o[c4 * 4 + 3] += p * vv.w;
                }
            }
            m = mt;
        }
        __syncthreads();
    }

    float inv = 1.f / l;
    float* op = out + (size_t)(b * SEQ + row) * EMB + h * HDIM;
#pragma unroll
    for (int c4 = 0; c4 < 16; c4++) {
        float4 v;
        v.x = o[c4 * 4 + 0] * inv;
        v.y = o[c4 * 4 + 1] * inv;
        v.z = o[c4 * 4 + 2] * inv;
        v.w = o[c4 * 4 + 3] * inv;
        *(float4*)(op + c4 * 4) = v;
    }
}

// Small helper kernels can't be used to fetch symbol addresses on host;
// use cudaGetSymbolAddress (not an allocation, capture-safe).
extern "C" void kernel_launch(void* const* d_in, const int* in_sizes, int n_in,
                              void* d_out, int out_size)
{
    const float* x     = (const float*)d_in[0];   // [8,1024,768]
    const float* Wqkv  = (const float*)d_in[1];   // [768, 2304]
    const float* bqkv  = (const float*)d_in[2];   // [2304]
    const float* Wout  = (const float*)d_in[3];   // [768, 768]
    const float* bout  = (const float*)d_in[4];   // [768]
    float* out = (float*)d_out;                   // [8,1024,768]

    float* qkv_ptr  = nullptr;
    float* attn_ptr = nullptr;
    cudaGetSymbolAddress((void**)&qkv_ptr,  g_qkv);
    cudaGetSymbolAddress((void**)&attn_ptr, g_attn);

    // 1) QKV projection: [8192,768] @ [768,2304] + b  -> g_qkv
    {
        dim3 grid(C3 / 64, MROWS / 64);
        sgemm_bias_kernel<<<grid, 256>>>(x, Wqkv, bqkv, qkv_ptr, MROWS, C3, EMB);
    }
    // 2) Causal attention -> g_attn
    {
        dim3 grid(SEQ / 128, BATCH * NHEAD);
        attn_kernel<<<grid, 128>>>(qkv_ptr, attn_ptr);
    }
    // 3) Output projection: [8192,768] @ [768,768] + b -> out
    {
        dim3 grid(EMB / 64, MROWS / 64);
        sgemm_bias_kernel<<<grid, 256>>>(attn_ptr, Wout, bout, out, MROWS, EMB, EMB);
    }
}

// round 2
// speedup vs baseline: 1.1953x; 1.1953x over previous
#include <cuda_runtime.h>
#include <cstdint>

// Problem constants
#define BATCH 8
#define SEQ   1024
#define EMB   768
#define NHEAD 12
#define HDIM  64
#define C3    (3*EMB)          // 2304
#define MROWS (BATCH*SEQ)      // 8192

// Scratch (module-load allocated, allowed by harness rules)
__device__ float g_qkv[(size_t)MROWS * C3];    // [8192, 2304]
__device__ float g_attn[(size_t)MROWS * EMB];  // [8192, 768]

// ---------------------------------------------------------------------------
// Tiled SGEMM with bias: C[M,N] = A[M,K] @ B[K,N] + bias[N]
// BM=BN=128, BK=16, 256 threads, 8x8 microtile per thread (split 2x 4-vec).
// Register prefetch of next global tile. Requires M%128==0, N%128==0, K%16==0.
// ---------------------------------------------------------------------------
__global__ __launch_bounds__(256, 2)
void sgemm_bias_128(const float* __restrict__ A,
                    const float* __restrict__ B,
                    const float* __restrict__ bias,
                    float* __restrict__ C,
                    int M, int N, int K)
{
    __shared__ float As[16][132];   // transposed A tile, padded (2-way max conflict)
    __shared__ float Bs[16][128];

    int tid = threadIdx.x;
    int tx = tid & 15;              // 0..15 -> N direction
    int ty = tid >> 4;              // 0..15 -> M direction
    int rowBase = blockIdx.y * 128;
    int colBase = blockIdx.x * 128;

    const float* Ab = A + (size_t)rowBase * K;
    const float* Bb = B + colBase;

    // Global-load index mapping (each thread: 2 float4 of A, 2 float4 of B)
    int ar0 = tid >> 2;             // 0..63
    int ak0 = (tid & 3) * 4;        // 0,4,8,12
    int ar1 = ar0 + 64;             // 64..127
    int br0 = tid >> 5;             // 0..7
    int bc  = (tid & 31) * 4;       // 0..124
    int br1 = br0 + 8;              // 8..15

    float4 a0 = *(const float4*)&Ab[(size_t)ar0 * K + ak0];
    float4 a1 = *(const float4*)&Ab[(size_t)ar1 * K + ak0];
    float4 b0 = *(const float4*)&Bb[(size_t)br0 * N + bc];
    float4 b1 = *(const float4*)&Bb[(size_t)br1 * N + bc];

    float acc[8][8];
#pragma unroll
    for (int i = 0; i < 8; i++)
#pragma unroll
        for (int j = 0; j < 8; j++) acc[i][j] = 0.f;

    int nk = K / 16;
    for (int t = 0; t < nk; t++) {
        // Commit prefetched tile to smem
        As[ak0 + 0][ar0] = a0.x; As[ak0 + 1][ar0] = a0.y;
        As[ak0 + 2][ar0] = a0.z; As[ak0 + 3][ar0] = a0.w;
        As[ak0 + 0][ar1] = a1.x; As[ak0 + 1][ar1] = a1.y;
        As[ak0 + 2][ar1] = a1.z; As[ak0 + 3][ar1] = a1.w;
        *(float4*)&Bs[br0][bc] = b0;
        *(float4*)&Bs[br1][bc] = b1;
        __syncthreads();

        // Prefetch next tile into registers (overlaps with compute)
        if (t + 1 < nk) {
            int k0 = (t + 1) * 16;
            a0 = *(const float4*)&Ab[(size_t)ar0 * K + k0 + ak0];
            a1 = *(const float4*)&Ab[(size_t)ar1 * K + k0 + ak0];
            b0 = *(const float4*)&Bb[(size_t)(k0 + br0) * N + bc];
            b1 = *(const float4*)&Bb[(size_t)(k0 + br1) * N + bc];
        }

#pragma unroll
        for (int k = 0; k < 16; k++) {
            float4 x0 = *(const float4*)&As[k][ty * 4];
            float4 x1 = *(const float4*)&As[k][64 + ty * 4];
            float4 y0 = *(const float4*)&Bs[k][tx * 4];
            float4 y1 = *(const float4*)&Bs[k][64 + tx * 4];
            float ar[8] = {x0.x, x0.y, x0.z, x0.w, x1.x, x1.y, x1.z, x1.w};
            float br[8] = {y0.x, y0.y, y0.z, y0.w, y1.x, y1.y, y1.z, y1.w};
#pragma unroll
            for (int i = 0; i < 8; i++)
#pragma unroll
                for (int j = 0; j < 8; j++)
                    acc[i][j] += ar[i] * br[j];
        }
        __syncthreads();
    }

    // Epilogue with bias; 2x2 blocks of 4x4 float4 stores
    float4 bv0 = *(const float4*)&bias[colBase + tx * 4];
    float4 bv1 = *(const float4*)&bias[colBase + 64 + tx * 4];
    float bb[8] = {bv0.x, bv0.y, bv0.z, bv0.w, bv1.x, bv1.y, bv1.z, bv1.w};
#pragma unroll
    for (int hi = 0; hi < 2; hi++) {
#pragma unroll
        for (int i = 0; i < 4; i++) {
            int row = rowBase + hi * 64 + ty * 4 + i;
            float* cp = &C[(size_t)row * N + colBase];
#pragma unroll
            for (int hj = 0; hj < 2; hj++) {
                float4 o;
                o.x = acc[hi * 4 + i][hj * 4 + 0] + bb[hj * 4 + 0];
                o.y = acc[hi * 4 + i][hj * 4 + 1] + bb[hj * 4 + 1];
                o.z = acc[hi * 4 + i][hj * 4 + 2] + bb[hj * 4 + 2];
                o.w = acc[hi * 4 + i][hj * 4 + 3] + bb[hj * 4 + 3];
                *(float4*)(cp + hj * 64 + tx * 4) = o;
            }
        }
    }
}

// ---------------------------------------------------------------------------
// Causal flash attention, fp32.
// Grid: (SEQ/128, BATCH*NHEAD). Block: 128 threads, 1 query row per thread.
// K/V streamed in 32-key tiles through shared memory; online softmax.
// qkv layout: [B*T, 3C] row-major; q at col h*64, k at C + h*64, v at 2C + h*64.
// Output written to g_attn [B*T, C] at col h*64.
// ---------------------------------------------------------------------------
__global__ __launch_bounds__(128)
void attn_kernel(const float* __restrict__ qkv, float* __restrict__ out)
{
    const int ROWS = 128, KT = 32;
    const float scale = 0.125f;   // 1/sqrt(64)

    int bh = blockIdx.y;
    int b  = bh / NHEAD;
    int h  = bh - b * NHEAD;
    int qbase = blockIdx.x * ROWS;
    int row = qbase + threadIdx.x;            // query index in [0, SEQ)

    __shared__ float Ks[KT][HDIM];
    __shared__ float Vs[KT][HDIM];

    // Load q row into registers
    float q[HDIM];
    {
        const float* qp = qkv + (size_t)(b * SEQ + row) * C3 + h * HDIM;
#pragma unroll
        for (int c4 = 0; c4 < 16; c4++) {
            float4 v = *(const float4*)(qp + c4 * 4);
            q[c4 * 4 + 0] = v.x; q[c4 * 4 + 1] = v.y;
            q[c4 * 4 + 2] = v.z; q[c4 * 4 + 3] = v.w;
        }
    }

    float o[HDIM];
#pragma unroll
    for (int c = 0; c < HDIM; c++) o[c] = 0.f;
    float m = -3.0e38f;
    float l = 0.f;

    int ntiles = (qbase + ROWS) / KT;   // keys needed: up to qbase+127

    for (int t = 0; t < ntiles; t++) {
        int kbase = t * KT;

        // Cooperative tile load: 32 keys x 64 floats for K and V (float4)
        for (int i = threadIdx.x; i < KT * 16; i += ROWS) {
            int r  = i >> 4;
            int cq = i & 15;
            size_t base = (size_t)(b * SEQ + kbase + r) * C3 + h * HDIM + cq * 4;
            *(float4*)&Ks[r][cq * 4] = *(const float4*)(qkv + base + EMB);
            *(float4*)&Vs[r][cq * 4] = *(const float4*)(qkv + base + 2 * EMB);
        }
        __syncthreads();

        if (kbase <= row) {
            // Scores for this tile
            float s[KT];
#pragma unroll 4
            for (int j = 0; j < KT; j++) {
                float a0 = 0.f, a1 = 0.f, a2 = 0.f, a3 = 0.f;
#pragma unroll
                for (int c4 = 0; c4 < 16; c4++) {
                    float4 kk = *(const float4*)&Ks[j][c4 * 4];
                    a0 += q[c4 * 4 + 0] * kk.x;
                    a1 += q[c4 * 4 + 1] * kk.y;
                    a2 += q[c4 * 4 + 2] * kk.z;
                    a3 += q[c4 * 4 + 3] * kk.w;
                }
                s[j] = (a0 + a1 + a2 + a3) * scale;
            }
            // Causal mask within tile
            if (kbase + KT - 1 > row) {
#pragma unroll
                for (int j = 0; j < KT; j++)
                    if (kbase + j > row) s[j] = -3.0e38f;
            }
            // Online softmax update
            float mt = m;
#pragma unroll
            for (int j = 0; j < KT; j++) mt = fmaxf(mt, s[j]);
            float corr = __expf(m - mt);
            l *= corr;
#pragma unroll
            for (int c = 0; c < HDIM; c++) o[c] *= corr;
#pragma unroll 4
            for (int j = 0; j < KT; j++) {
                float p = __expf(s[j] - mt);
                l += p;
#pragma unroll
                for (int c4 = 0; c4 < 16; c4++) {
                    float4 vv = *(const float4*)&Vs[j][c4 * 4];
                    o[c4 * 4 + 0] += p * vv.x;
                    o[c4 * 4 + 1] += p * vv.y;
                    o[c4 * 4 + 2] += p * vv.z;
                    o[c4 * 4 + 3] += p * vv.w;
                }
            }
            m = mt;
        }
        __syncthreads();
    }

    float inv = 1.f / l;
    float* op = out + (size_t)(b * SEQ + row) * EMB + h * HDIM;
#pragma unroll
    for (int c4 = 0; c4 < 16; c4++) {
        float4 v;
        v.x = o[c4 * 4 + 0] * inv;
        v.y = o[c4 * 4 + 1] * inv;
        v.z = o[c4 * 4 + 2] * inv;
        v.w = o[c4 * 4 + 3] * inv;
        *(float4*)(op + c4 * 4) = v;
    }
}

extern "C" void kernel_launch(void* const* d_in, const int* in_sizes, int n_in,
                              void* d_out, int out_size)
{
    const float* x     = (const float*)d_in[0];   // [8,1024,768]
    const float* Wqkv  = (const float*)d_in[1];   // [768, 2304]
    const float* bqkv  = (const float*)d_in[2];   // [2304]
    const float* Wout  = (const float*)d_in[3];   // [768, 768]
    const float* bout  = (const float*)d_in[4];   // [768]
    float* out = (float*)d_out;                   // [8,1024,768]

    float* qkv_ptr  = nullptr;
    float* attn_ptr = nullptr;
    cudaGetSymbolAddress((void**)&qkv_ptr,  g_qkv);
    cudaGetSymbolAddress((void**)&attn_ptr, g_attn);

    // 1) QKV projection: [8192,768] @ [768,2304] + b  -> g_qkv
    {
        dim3 grid(C3 / 128, MROWS / 128);
        sgemm_bias_128<<<grid, 256>>>(x, Wqkv, bqkv, qkv_ptr, MROWS, C3, EMB);
    }
    // 2) Causal attention -> g_attn
    {
        dim3 grid(SEQ / 128, BATCH * NHEAD);
        attn_kernel<<<grid, 128>>>(qkv_ptr, attn_ptr);
    }
    // 3) Output projection: [8192,768] @ [768,768] + b -> out
    {
        dim3 grid(EMB / 128, MROWS / 128);
        sgemm_bias_128<<<grid, 256>>>(attn_ptr, Wout, bout, out, MROWS, EMB, EMB);
    }
}

// round 4
// speedup vs baseline: 1.5575x; 1.3030x over previous
#include <cuda_runtime.h>
#include <cuda_bf16.h>
#include <cstdint>

// Problem constants
#define BATCH 8
#define SEQ   1024
#define EMB   768
#define NHEAD 12
#define HDIM  64
#define C3    (3*EMB)          // 2304
#define MROWS (BATCH*SEQ)      // 8192
#define NKB   24               // 768 / 32 k-blocks

// ---------------------------------------------------------------------------
// Scratch (static device arrays)
// ---------------------------------------------------------------------------
__device__ float g_qkv[(size_t)MROWS * C3];    // [8192, 2304] fp32
__device__ float g_attn[(size_t)MROWS * EMB];  // [8192, 768]  fp32

// Split-bf16 images, plain row-major.
// A-images: [rows][768]
__device__ __nv_bfloat16 g_xa_hi[(size_t)MROWS * EMB];
__device__ __nv_bfloat16 g_xa_lo[(size_t)MROWS * EMB];
__device__ __nv_bfloat16 g_at_hi[(size_t)MROWS * EMB];
__device__ __nv_bfloat16 g_at_lo[(size_t)MROWS * EMB];
// B-images (weights transposed to [N][K=768])
__device__ __nv_bfloat16 g_wq_hi[(size_t)C3 * EMB];
__device__ __nv_bfloat16 g_wq_lo[(size_t)C3 * EMB];
__device__ __nv_bfloat16 g_wo_hi[(size_t)EMB * EMB];
__device__ __nv_bfloat16 g_wo_lo[(size_t)EMB * EMB];

// ---------------------------------------------------------------------------
// Helpers
// ---------------------------------------------------------------------------
__device__ __forceinline__ uint32_t smem_u32(const void* p) {
    uint32_t a;
    asm("{ .reg .u64 t; cvta.to.shared.u64 t, %1; cvt.u32.u64 %0, t; }"
        : "=r"(a) : "l"(p));
    return a;
}

__device__ __forceinline__ void ldm4(uint32_t* r, uint32_t addr) {
    asm volatile("ldmatrix.sync.aligned.m8n8.x4.shared.b16 {%0,%1,%2,%3}, [%4];"
                 : "=r"(r[0]), "=r"(r[1]), "=r"(r[2]), "=r"(r[3]) : "r"(addr));
}

__device__ __forceinline__ void mma16816(float* c, const uint32_t* a,
                                         uint32_t b0, uint32_t b1) {
    asm volatile(
        "mma.sync.aligned.m16n8k16.row.col.f32.bf16.bf16.f32 "
        "{%0,%1,%2,%3},{%4,%5,%6,%7},{%8,%9},{%0,%1,%2,%3};"
        : "+f"(c[0]), "+f"(c[1]), "+f"(c[2]), "+f"(c[3])
        : "r"(a[0]), "r"(a[1]), "r"(a[2]), "r"(a[3]), "r"(b0), "r"(b1));
}

#define CP_ASYNC16(dst, src) \
    asm volatile("cp.async.cg.shared.global [%0], [%1], 16;" :: "r"(dst), "l"(src))
#define CP_COMMIT() asm volatile("cp.async.commit_group;" ::: "memory")
#define CP_WAIT1()  asm volatile("cp.async.wait_group 1;" ::: "memory")

// ---------------------------------------------------------------------------
// Conversion kernels: fp32 -> split bf16 (hi + lo)
// ---------------------------------------------------------------------------
__device__ __forceinline__ void split_bf16(float v, __nv_bfloat16& h, __nv_bfloat16& l) {
    h = __float2bfloat16(v);
    l = __float2bfloat16(v - __bfloat162float(h));
}

// Elementwise: in [rows*768] f32 -> hi/lo [rows*768] bf16 row-major
__global__ __launch_bounds__(256)
void conv_A(const float4* __restrict__ in,
            __nv_bfloat16* __restrict__ hi, __nv_bfloat16* __restrict__ lo,
            int total4)
{
    int idx = blockIdx.x * 256 + threadIdx.x;
    if (idx >= total4) return;
    float4 v = in[idx];
    __nv_bfloat16 h0, h1, h2, h3, l0, l1, l2, l3;
    split_bf16(v.x, h0, l0); split_bf16(v.y, h1, l1);
    split_bf16(v.z, h2, l2); split_bf16(v.w, h3, l3);
    uint2 ph, pl;
    ph.x = ((uint32_t)__bfloat16_as_ushort(h1) << 16) | __bfloat16_as_ushort(h0);
    ph.y = ((uint32_t)__bfloat16_as_ushort(h3) << 16) | __bfloat16_as_ushort(h2);
    pl.x = ((uint32_t)__bfloat16_as_ushort(l1) << 16) | __bfloat16_as_ushort(l0);
    pl.y = ((uint32_t)__bfloat16_as_ushort(l3) << 16) | __bfloat16_as_ushort(l2);
    ((uint2*)hi)[idx] = ph;
    ((uint2*)lo)[idx] = pl;
}

// Transpose: W [768][Nout] f32 -> Bimg [Nout][768] bf16 hi/lo
__global__ __launch_bounds__(256)
void conv_B(const float4* __restrict__ in,
            __nv_bfloat16* __restrict__ hi, __nv_bfloat16* __restrict__ lo,
            int Nout)
{
    int nq4 = Nout / 4;
    int idx = blockIdx.x * 256 + threadIdx.x;
    if (idx >= 768 * nq4) return;
    int k = idx / nq4;
    int n = (idx - k * nq4) * 4;
    float4 v = in[idx];
    float vals[4] = {v.x, v.y, v.z, v.w};
#pragma unroll
    for (int j = 0; j < 4; j++) {
        __nv_bfloat16 h, l;
        split_bf16(vals[j], h, l);
        hi[(size_t)(n + j) * EMB + k] = h;
        lo[(size_t)(n + j) * EMB + k] = l;
    }
}

// ---------------------------------------------------------------------------
// HMMA split-bf16 GEMM: C[M,N] = A[M,768] @ B[N,768]^T + bias
// CTA: 128x128 tile, 256 threads (8 warps, each 64m x 32n).
// Smem: 2 stages x (Ah, Al, Bh, Bl), each [128 rows][32 k] bf16 padded to 80B rows.
// ---------------------------------------------------------------------------
#define ARR_B   10240            // bytes per array (128 * 80)
#define STAGE_B 40960            // 4 arrays
#define SMEM_B  (2 * STAGE_B)    // 81920

__device__ __forceinline__ void issue_copy(
    uint32_t sb, int stage,
    const __nv_bfloat16* __restrict__ Ah, const __nv_bfloat16* __restrict__ Al,
    const __nv_bfloat16* __restrict__ Bh, const __nv_bfloat16* __restrict__ Bl,
    int mB, int nB, int kb, int tid)
{
    uint32_t dstBase = sb + stage * STAGE_B;
#pragma unroll
    for (int i = 0; i < 8; i++) {
        int idx = tid + i * 256;
        int arr = idx >> 9;
        int w   = idx & 511;
        int row = w >> 2;
        int ch  = w & 3;
        const __nv_bfloat16* src;
        int rbase;
        if      (arr == 0) { src = Ah; rbase = mB; }
        else if (arr == 1) { src = Al; rbase = mB; }
        else if (arr == 2) { src = Bh; rbase = nB; }
        else               { src = Bl; rbase = nB; }
        const void* g = src + (size_t)(rbase + row) * EMB + kb * 32 + ch * 8;
        uint32_t d = dstBase + arr * ARR_B + row * 80 + ch * 16;
        CP_ASYNC16(d, g);
    }
    CP_COMMIT();
}

__global__ __launch_bounds__(256, 2)
void hmma_gemm(const __nv_bfloat16* __restrict__ Ah, const __nv_bfloat16* __restrict__ Al,
               const __nv_bfloat16* __restrict__ Bh, const __nv_bfloat16* __restrict__ Bl,
               const float* __restrict__ bias, float* __restrict__ C, int Nout)
{
    extern __shared__ char smem[];
    uint32_t sb = smem_u32(smem);
    int tid  = threadIdx.x;
    int lane = tid & 31;
    int wid  = tid >> 5;
    int wm = (wid & 1) * 64;     // warp m offset within tile
    int wn = (wid >> 1) * 32;    // warp n offset within tile
    int mB = blockIdx.y * 128;
    int nB = blockIdx.x * 128;

    // ldmatrix lane addressing components
    int lrow = lane & 15;
    int lkb  = (lane >> 4) * 16;  // 16B (8 bf16) k-offset

    float acc[4][4][4];
#pragma unroll
    for (int a = 0; a < 4; a++)
#pragma unroll
        for (int b = 0; b < 4; b++)
#pragma unroll
            for (int c = 0; c < 4; c++) acc[a][b][c] = 0.f;

    // Prologue: fill both stages
    issue_copy(sb, 0, Ah, Al, Bh, Bl, mB, nB, 0, tid);
    issue_copy(sb, 1, Ah, Al, Bh, Bl, mB, nB, 1, tid);

    for (int kb = 0; kb < NKB; kb++) {
        CP_WAIT1();
        __syncthreads();
        int st = kb & 1;
        uint32_t aBase = sb + st * STAGE_B + (wm + lrow) * 80 + lkb;
        uint32_t bBase = sb + st * STAGE_B + 2 * ARR_B + (wn + lrow) * 80 + lkb;

#pragma unroll
        for (int ks = 0; ks < 2; ks++) {
            uint32_t bh[2][4], bl[2][4];
            ldm4(bh[0], bBase + ks * 32);
            ldm4(bh[1], bBase + 1280 + ks * 32);
            ldm4(bl[0], bBase + ARR_B + ks * 32);
            ldm4(bl[1], bBase + ARR_B + 1280 + ks * 32);
#pragma unroll
            for (int mt = 0; mt < 4; mt++) {
                uint32_t ah[4], al[4];
                ldm4(ah, aBase + mt * 1280 + ks * 32);
                ldm4(al, aBase + ARR_B + mt * 1280 + ks * 32);
#pragma unroll
                for (int np = 0; np < 2; np++) {
#pragma unroll
                    for (int h = 0; h < 2; h++) {
                        int nt = np * 2 + h;
                        uint32_t b0h = bh[np][h], b1h = bh[np][h + 2];
                        uint32_t b0l = bl[np][h], b1l = bl[np][h + 2];
                        mma16816(acc[mt][nt], ah, b0h, b1h);   // hi*hi
                        mma16816(acc[mt][nt], al, b0h, b1h);   // lo*hi
                        mma16816(acc[mt][nt], ah, b0l, b1l);   // hi*lo
                    }
                }
            }
        }
        __syncthreads();
        if (kb + 2 < NKB) issue_copy(sb, st, Ah, Al, Bh, Bl, mB, nB, kb + 2, tid);
        else CP_COMMIT();
    }

    // Epilogue
#pragma unroll
    for (int mt = 0; mt < 4; mt++) {
#pragma unroll
        for (int nt = 0; nt < 4; nt++) {
            int r0 = mB + wm + mt * 16 + (lane >> 2);
            int c0 = nB + wn + nt * 8 + (lane & 3) * 2;
            float bx = bias[c0], by = bias[c0 + 1];
            float2 o0, o1;
            o0.x = acc[mt][nt][0] + bx; o0.y = acc[mt][nt][1] + by;
            o1.x = acc[mt][nt][2] + bx; o1.y = acc[mt][nt][3] + by;
            *(float2*)&C[(size_t)r0 * Nout + c0] = o0;
            *(float2*)&C[(size_t)(r0 + 8) * Nout + c0] = o1;
        }
    }
}

// ---------------------------------------------------------------------------
// Causal flash attention, fp32 (unchanged — R2 validated).
// ---------------------------------------------------------------------------
__global__ __launch_bounds__(128)
void attn_kernel(const float* __restrict__ qkv, float* __restrict__ out)
{
    const int ROWS = 128, KT = 32;
    const float scale = 0.125f;

    int bh = blockIdx.y;
    int b  = bh / NHEAD;
    int h  = bh - b * NHEAD;
    int qbase = blockIdx.x * ROWS;
    int row = qbase + threadIdx.x;

    __shared__ float Ks[KT][HDIM];
    __shared__ float Vs[KT][HDIM];

    float q[HDIM];
    {
        const float* qp = qkv + (size_t)(b * SEQ + row) * C3 + h * HDIM;
#pragma unroll
        for (int c4 = 0; c4 < 16; c4++) {
            float4 v = *(const float4*)(qp + c4 * 4);
            q[c4 * 4 + 0] = v.x; q[c4 * 4 + 1] = v.y;
            q[c4 * 4 + 2] = v.z; q[c4 * 4 + 3] = v.w;
        }
    }

    float o[HDIM];
#pragma unroll
    for (int c = 0; c < HDIM; c++) o[c] = 0.f;
    float m = -3.0e38f;
    float l = 0.f;

    int ntiles = (qbase + ROWS) / KT;

    for (int t = 0; t < ntiles; t++) {
        int kbase = t * KT;
        for (int i = threadIdx.x; i < KT * 16; i += ROWS) {
            int r  = i >> 4;
            int cq = i & 15;
            size_t base = (size_t)(b * SEQ + kbase + r) * C3 + h * HDIM + cq * 4;
            *(float4*)&Ks[r][cq * 4] = *(const float4*)(qkv + base + EMB);
            *(float4*)&Vs[r][cq * 4] = *(const float4*)(qkv + base + 2 * EMB);
        }
        __syncthreads();

        if (kbase <= row) {
            float s[KT];
#pragma unroll 4
            for (int j = 0; j < KT; j++) {
                float a0 = 0.f, a1 = 0.f, a2 = 0.f, a3 = 0.f;
#pragma unroll
                for (int c4 = 0; c4 < 16; c4++) {
                    float4 kk = *(const float4*)&Ks[j][c4 * 4];
                    a0 += q[c4 * 4 + 0] * kk.x;
                    a1 += q[c4 * 4 + 1] * kk.y;
                    a2 += q[c4 * 4 + 2] * kk.z;
                    a3 += q[c4 * 4 + 3] * kk.w;
                }
                s[j] = (a0 + a1 + a2 + a3) * scale;
            }
            if (kbase + KT - 1 > row) {
#pragma unroll
                for (int j = 0; j < KT; j++)
                    if (kbase + j > row) s[j] = -3.0e38f;
            }
            float mt = m;
#pragma unroll
            for (int j = 0; j < KT; j++) mt = fmaxf(mt, s[j]);
            float corr = __expf(m - mt);
            l *= corr;
#pragma unroll
            for (int c = 0; c < HDIM; c++) o[c] *= corr;
#pragma unroll 4
            for (int j = 0; j < KT; j++) {
                float p = __expf(s[j] - mt);
                l += p;
#pragma unroll
                for (int c4 = 0; c4 < 16; c4++) {
                    float4 vv = *(const float4*)&Vs[j][c4 * 4];
                    o[c4 * 4 + 0] += p * vv.x;
                    o[c4 * 4 + 1] += p * vv.y;
                    o[c4 * 4 + 2] += p * vv.z;
                    o[c4 * 4 + 3] += p * vv.w;
                }
            }
            m = mt;
        }
        __syncthreads();
    }

    float inv = 1.f / l;
    float* op = out + (size_t)(b * SEQ + row) * EMB + h * HDIM;
#pragma unroll
    for (int c4 = 0; c4 < 16; c4++) {
        float4 v;
        v.x = o[c4 * 4 + 0] * inv;
        v.y = o[c4 * 4 + 1] * inv;
        v.z = o[c4 * 4 + 2] * inv;
        v.w = o[c4 * 4 + 3] * inv;
        *(float4*)(op + c4 * 4) = v;
    }
}

// ---------------------------------------------------------------------------
extern "C" void kernel_launch(void* const* d_in, const int* in_sizes, int n_in,
                              void* d_out, int out_size)
{
    const float* x     = (const float*)d_in[0];
    const float* Wqkv  = (const float*)d_in[1];
    const float* bqkv  = (const float*)d_in[2];
    const float* Wout  = (const float*)d_in[3];
    const float* bout  = (const float*)d_in[4];
    float* out = (float*)d_out;

    float *qkv_p, *attn_p;
    __nv_bfloat16 *xah, *xal, *ath, *atl, *wqh, *wql, *woh, *wol;
    cudaGetSymbolAddress((void**)&qkv_p,  g_qkv);
    cudaGetSymbolAddress((void**)&attn_p, g_attn);
    cudaGetSymbolAddress((void**)&xah, g_xa_hi);
    cudaGetSymbolAddress((void**)&xal, g_xa_lo);
    cudaGetSymbolAddress((void**)&ath, g_at_hi);
    cudaGetSymbolAddress((void**)&atl, g_at_lo);
    cudaGetSymbolAddress((void**)&wqh, g_wq_hi);
    cudaGetSymbolAddress((void**)&wql, g_wq_lo);
    cudaGetSymbolAddress((void**)&woh, g_wo_hi);
    cudaGetSymbolAddress((void**)&wol, g_wo_lo);

    cudaFuncSetAttribute(hmma_gemm, cudaFuncAttributeMaxDynamicSharedMemorySize, SMEM_B);

    // Convert inputs to split-bf16 images
    conv_A<<<(MROWS * 192 + 255) / 256, 256>>>((const float4*)x, xah, xal, MROWS * 192);
    conv_B<<<(768 * (C3 / 4) + 255) / 256, 256>>>((const float4*)Wqkv, wqh, wql, C3);
    conv_B<<<(768 * (EMB / 4) + 255) / 256, 256>>>((const float4*)Wout, woh, wol, EMB);

    // 1) QKV projection (HMMA split-bf16)
    {
        dim3 grid(C3 / 128, MROWS / 128);
        hmma_gemm<<<grid, 256, SMEM_B>>>(xah, xal, wqh, wql, bqkv, qkv_p, C3);
    }
    // 2) Causal attention (fp32 SIMT)
    {
        dim3 grid(SEQ / 128, BATCH * NHEAD);
        attn_kernel<<<grid, 128>>>(qkv_p, attn_p);
    }
    // 3) Convert attention output, then output projection (HMMA split-bf16)
    conv_A<<<(MROWS * 192 + 255) / 256, 256>>>((const float4*)attn_p, ath, atl, MROWS * 192);
    {
        dim3 grid(EMB / 128, MROWS / 128);
        hmma_gemm<<<grid, 256, SMEM_B>>>(ath, atl, woh, wol, bout, out, EMB);
    }
}

// round 5
// speedup vs baseline: 2.7131x; 1.7420x over previous
#include <cuda_runtime.h>
#include <cuda_bf16.h>
#include <cstdint>

// Problem constants
#define BATCH 8
#define SEQ   1024
#define EMB   768
#define NHEAD 12
#define HDIM  64
#define C3    (3*EMB)          // 2304
#define MROWS (BATCH*SEQ)      // 8192
#define NKB   24               // 768 / 32 k-blocks
#define NBH   (BATCH*NHEAD)    // 96

// ---------------------------------------------------------------------------
// Scratch (static device arrays)
// ---------------------------------------------------------------------------
// Split-bf16 images, plain row-major.
__device__ __nv_bfloat16 g_xa_hi[(size_t)MROWS * EMB];
__device__ __nv_bfloat16 g_xa_lo[(size_t)MROWS * EMB];
__device__ __nv_bfloat16 g_at_hi[(size_t)MROWS * EMB];
__device__ __nv_bfloat16 g_at_lo[(size_t)MROWS * EMB];
// Weights transposed to [N][K=768]
__device__ __nv_bfloat16 g_wq_hi[(size_t)C3 * EMB];
__device__ __nv_bfloat16 g_wq_lo[(size_t)C3 * EMB];
__device__ __nv_bfloat16 g_wo_hi[(size_t)EMB * EMB];
__device__ __nv_bfloat16 g_wo_lo[(size_t)EMB * EMB];
// QKV rearranged: [(bh*3 + which)][T][64], which: 0=q,1=k,2=v
__device__ __nv_bfloat16 g_qkvr_hi[(size_t)NBH * 3 * SEQ * HDIM];
__device__ __nv_bfloat16 g_qkvr_lo[(size_t)NBH * 3 * SEQ * HDIM];

// ---------------------------------------------------------------------------
// Helpers
// ---------------------------------------------------------------------------
__device__ __forceinline__ uint32_t smem_u32(const void* p) {
    uint32_t a;
    asm("{ .reg .u64 t; cvta.to.shared.u64 t, %1; cvt.u32.u64 %0, t; }"
        : "=r"(a) : "l"(p));
    return a;
}

__device__ __forceinline__ void ldm4(uint32_t* r, uint32_t addr) {
    asm volatile("ldmatrix.sync.aligned.m8n8.x4.shared.b16 {%0,%1,%2,%3}, [%4];"
                 : "=r"(r[0]), "=r"(r[1]), "=r"(r[2]), "=r"(r[3]) : "r"(addr));
}
__device__ __forceinline__ void ldm4t(uint32_t* r, uint32_t addr) {
    asm volatile("ldmatrix.sync.aligned.m8n8.x4.trans.shared.b16 {%0,%1,%2,%3}, [%4];"
                 : "=r"(r[0]), "=r"(r[1]), "=r"(r[2]), "=r"(r[3]) : "r"(addr));
}

__device__ __forceinline__ void mma16816(float* c, const uint32_t* a,
                                         uint32_t b0, uint32_t b1) {
    asm volatile(
        "mma.sync.aligned.m16n8k16.row.col.f32.bf16.bf16.f32 "
        "{%0,%1,%2,%3},{%4,%5,%6,%7},{%8,%9},{%0,%1,%2,%3};"
        : "+f"(c[0]), "+f"(c[1]), "+f"(c[2]), "+f"(c[3])
        : "r"(a[0]), "r"(a[1]), "r"(a[2]), "r"(a[3]), "r"(b0), "r"(b1));
}

#define CP_ASYNC16(dst, src) \
    asm volatile("cp.async.cg.shared.global [%0], [%1], 16;" :: "r"(dst), "l"(src))
#define CP_COMMIT() asm volatile("cp.async.commit_group;" ::: "memory")
#define CP_WAIT1()  asm volatile("cp.async.wait_group 1;" ::: "memory")
#define CP_WAIT0()  asm volatile("cp.async.wait_group 0;" ::: "memory")

__device__ __forceinline__ void split_bf16(float v, __nv_bfloat16& h, __nv_bfloat16& l) {
    h = __float2bfloat16(v);
    l = __float2bfloat16(v - __bfloat162float(h));
}
__device__ __forceinline__ uint32_t pack2(__nv_bfloat16 lo16, __nv_bfloat16 hi16) {
    return ((uint32_t)__bfloat16_as_ushort(hi16) << 16) | __bfloat16_as_ushort(lo16);
}

// ---------------------------------------------------------------------------
// Conversion kernels
// ---------------------------------------------------------------------------
__global__ __launch_bounds__(256)
void conv_A(const float4* __restrict__ in,
            __nv_bfloat16* __restrict__ hi, __nv_bfloat16* __restrict__ lo,
            int total4)
{
    int idx = blockIdx.x * 256 + threadIdx.x;
    if (idx >= total4) return;
    float4 v = in[idx];
    __nv_bfloat16 h0, h1, h2, h3, l0, l1, l2, l3;
    split_bf16(v.x, h0, l0); split_bf16(v.y, h1, l1);
    split_bf16(v.z, h2, l2); split_bf16(v.w, h3, l3);
    uint2 ph, pl;
    ph.x = pack2(h0, h1); ph.y = pack2(h2, h3);
    pl.x = pack2(l0, l1); pl.y = pack2(l2, l3);
    ((uint2*)hi)[idx] = ph;
    ((uint2*)lo)[idx] = pl;
}

__global__ __launch_bounds__(256)
void conv_B(const float4* __restrict__ in,
            __nv_bfloat16* __restrict__ hi, __nv_bfloat16* __restrict__ lo,
            int Nout)
{
    int nq4 = Nout / 4;
    int idx = blockIdx.x * 256 + threadIdx.x;
    if (idx >= 768 * nq4) return;
    int k = idx / nq4;
    int n = (idx - k * nq4) * 4;
    float4 v = in[idx];
    float vals[4] = {v.x, v.y, v.z, v.w};
#pragma unroll
    for (int j = 0; j < 4; j++) {
        __nv_bfloat16 h, l;
        split_bf16(vals[j], h, l);
        hi[(size_t)(n + j) * EMB + k] = h;
        lo[(size_t)(n + j) * EMB + k] = l;
    }
}

// ---------------------------------------------------------------------------
// HMMA split-bf16 GEMM core (identical mainloop to R4; two epilogue variants)
// ---------------------------------------------------------------------------
#define ARR_B   10240
#define STAGE_B 40960
#define SMEM_B  (2 * STAGE_B)

__device__ __forceinline__ void issue_copy(
    uint32_t sb, int stage,
    const __nv_bfloat16* __restrict__ Ah, const __nv_bfloat16* __restrict__ Al,
    const __nv_bfloat16* __restrict__ Bh, const __nv_bfloat16* __restrict__ Bl,
    int mB, int nB, int kb, int tid)
{
    uint32_t dstBase = sb + stage * STAGE_B;
#pragma unroll
    for (int i = 0; i < 8; i++) {
        int idx = tid + i * 256;
        int arr = idx >> 9;
        int w   = idx & 511;
        int row = w >> 2;
        int ch  = w & 3;
        const __nv_bfloat16* src;
        int rbase;
        if      (arr == 0) { src = Ah; rbase = mB; }
        else if (arr == 1) { src = Al; rbase = mB; }
        else if (arr == 2) { src = Bh; rbase = nB; }
        else               { src = Bl; rbase = nB; }
        const void* g = src + (size_t)(rbase + row) * EMB + kb * 32 + ch * 8;
        uint32_t d = dstBase + arr * ARR_B + row * 80 + ch * 16;
        CP_ASYNC16(d, g);
    }
    CP_COMMIT();
}

__device__ __forceinline__ void gemm_mainloop(
    uint32_t sb, int tid, int lane, int wm, int wn, int mB, int nB,
    const __nv_bfloat16* Ah, const __nv_bfloat16* Al,
    const __nv_bfloat16* Bh, const __nv_bfloat16* Bl,
    float acc[4][4][4])
{
    int lrow = lane & 15;
    int lkb  = (lane >> 4) * 16;

    issue_copy(sb, 0, Ah, Al, Bh, Bl, mB, nB, 0, tid);
    issue_copy(sb, 1, Ah, Al, Bh, Bl, mB, nB, 1, tid);

    for (int kb = 0; kb < NKB; kb++) {
        CP_WAIT1();
        __syncthreads();
        int st = kb & 1;
        uint32_t aBase = sb + st * STAGE_B + (wm + lrow) * 80 + lkb;
        uint32_t bBase = sb + st * STAGE_B + 2 * ARR_B + (wn + lrow) * 80 + lkb;

#pragma unroll
        for (int ks = 0; ks < 2; ks++) {
            uint32_t bh[2][4], bl[2][4];
            ldm4(bh[0], bBase + ks * 32);
            ldm4(bh[1], bBase + 1280 + ks * 32);
            ldm4(bl[0], bBase + ARR_B + ks * 32);
            ldm4(bl[1], bBase + ARR_B + 1280 + ks * 32);
#pragma unroll
            for (int mt = 0; mt < 4; mt++) {
                uint32_t ah[4], al[4];
                ldm4(ah, aBase + mt * 1280 + ks * 32);
                ldm4(al, aBase + ARR_B + mt * 1280 + ks * 32);
#pragma unroll
                for (int np = 0; np < 2; np++) {
#pragma unroll
                    for (int h = 0; h < 2; h++) {
                        int nt = np * 2 + h;
                        mma16816(acc[mt][nt], ah, bh[np][h], bh[np][h + 2]);
                        mma16816(acc[mt][nt], al, bh[np][h], bh[np][h + 2]);
                        mma16816(acc[mt][nt], ah, bl[np][h], bl[np][h + 2]);
                    }
                }
            }
        }
        __syncthreads();
        if (kb + 2 < NKB) issue_copy(sb, st, Ah, Al, Bh, Bl, mB, nB, kb + 2, tid);
        else CP_COMMIT();
    }
}

// Variant 1: QKV projection — epilogue writes split-bf16 rearranged [bh][which][T][64]
__global__ __launch_bounds__(256, 2)
void hmma_gemm_qkv(const __nv_bfloat16* __restrict__ Ah, const __nv_bfloat16* __restrict__ Al,
                   const __nv_bfloat16* __restrict__ Bh, const __nv_bfloat16* __restrict__ Bl,
                   const float* __restrict__ bias,
                   __nv_bfloat16* __restrict__ Ohi, __nv_bfloat16* __restrict__ Olo)
{
    extern __shared__ char smem[];
    uint32_t sb = smem_u32(smem);
    int tid = threadIdx.x, lane = tid & 31, wid = tid >> 5;
    int wm = (wid & 1) * 64, wn = (wid >> 1) * 32;
    int mB = blockIdx.y * 128, nB = blockIdx.x * 128;

    float acc[4][4][4];
#pragma unroll
    for (int a = 0; a < 4; a++)
#pragma unroll
        for (int b = 0; b < 4; b++)
#pragma unroll
            for (int c = 0; c < 4; c++) acc[a][b][c] = 0.f;

    gemm_mainloop(sb, tid, lane, wm, wn, mB, nB, Ah, Al, Bh, Bl, acc);

    int b_ = mB / SEQ;   // whole 128-row tile lies in one batch
#pragma unroll
    for (int mt = 0; mt < 4; mt++) {
#pragma unroll
        for (int nt = 0; nt < 4; nt++) {
            int r0 = mB + wm + mt * 16 + (lane >> 2);
            int c0 = nB + wn + nt * 8 + (lane & 3) * 2;
            int which = c0 / EMB;
            int rem = c0 - which * EMB;
            int hh = rem >> 6;
            int d = rem & 63;
            size_t plane = ((size_t)((b_ * NHEAD + hh) * 3 + which)) * SEQ * HDIM;
            float bx = bias[c0], by = bias[c0 + 1];
            float v0 = acc[mt][nt][0] + bx, v1 = acc[mt][nt][1] + by;
            float v2 = acc[mt][nt][2] + bx, v3 = acc[mt][nt][3] + by;
            __nv_bfloat16 h0, h1, h2, h3, l0, l1, l2, l3;
            split_bf16(v0, h0, l0); split_bf16(v1, h1, l1);
            split_bf16(v2, h2, l2); split_bf16(v3, h3, l3);
            int t0 = r0 & (SEQ - 1);
            size_t i0 = plane + (size_t)t0 * HDIM + d;
            size_t i1 = plane + (size_t)(t0 + 8) * HDIM + d;
            *(uint32_t*)&Ohi[i0] = pack2(h0, h1);
            *(uint32_t*)&Olo[i0] = pack2(l0, l1);
            *(uint32_t*)&Ohi[i1] = pack2(h2, h3);
            *(uint32_t*)&Olo[i1] = pack2(l2, l3);
        }
    }
}

// Variant 2: output projection — fp32 epilogue to d_out
__global__ __launch_bounds__(256, 2)
void hmma_gemm_out(const __nv_bfloat16* __restrict__ Ah, const __nv_bfloat16* __restrict__ Al,
                   const __nv_bfloat16* __restrict__ Bh, const __nv_bfloat16* __restrict__ Bl,
                   const float* __restrict__ bias, float* __restrict__ C, int Nout)
{
    extern __shared__ char smem[];
    uint32_t sb = smem_u32(smem);
    int tid = threadIdx.x, lane = tid & 31, wid = tid >> 5;
    int wm = (wid & 1) * 64, wn = (wid >> 1) * 32;
    int mB = blockIdx.y * 128, nB = blockIdx.x * 128;

    float acc[4][4][4];
#pragma unroll
    for (int a = 0; a < 4; a++)
#pragma unroll
        for (int b = 0; b < 4; b++)
#pragma unroll
            for (int c = 0; c < 4; c++) acc[a][b][c] = 0.f;

    gemm_mainloop(sb, tid, lane, wm, wn, mB, nB, Ah, Al, Bh, Bl, acc);

#pragma unroll
    for (int mt = 0; mt < 4; mt++) {
#pragma unroll
        for (int nt = 0; nt < 4; nt++) {
            int r0 = mB + wm + mt * 16 + (lane >> 2);
            int c0 = nB + wn + nt * 8 + (lane & 3) * 2;
            float bx = bias[c0], by = bias[c0 + 1];
            float2 o0, o1;
            o0.x = acc[mt][nt][0] + bx; o0.y = acc[mt][nt][1] + by;
            o1.x = acc[mt][nt][2] + bx; o1.y = acc[mt][nt][3] + by;
            *(float2*)&C[(size_t)r0 * Nout + c0] = o0;
            *(float2*)&C[(size_t)(r0 + 8) * Nout + c0] = o1;
        }
    }
}

// ---------------------------------------------------------------------------
// Tensor-core causal flash attention (split-bf16, mma.sync).
// CTA: 128 q-rows for one (b,h); 8 warps x 16 rows. KV tiles of 64 keys,
// cp.async double-buffered. Output written as split-bf16 in out-proj A-format.
// ---------------------------------------------------------------------------
#define AT_PITCH 144
#define AT_ARR   (64 * AT_PITCH)     // 9216
#define AT_STAGE (4 * AT_ARR)        // 36864: k_hi,k_lo,v_hi,v_lo
#define AT_SMEM  (2 * AT_STAGE)      // 73728

__device__ __forceinline__ void attn_issue_kv(
    uint32_t sb, int stage,
    const __nv_bfloat16* kh, const __nv_bfloat16* kl,
    const __nv_bfloat16* vh, const __nv_bfloat16* vl,
    int kbase, int tid)
{
    uint32_t dstBase = sb + stage * AT_STAGE;
#pragma unroll
    for (int i = 0; i < 8; i++) {
        int idx = tid + i * 256;
        int arr = idx >> 9;
        int rem = idx & 511;
        int row = rem >> 3;
        int ch  = rem & 7;
        const __nv_bfloat16* src = (arr == 0) ? kh : (arr == 1) ? kl
                                 : (arr == 2) ? vh : vl;
        const void* g = src + (size_t)(kbase + row) * HDIM + ch * 8;
        CP_ASYNC16(dstBase + arr * AT_ARR + row * AT_PITCH + ch * 16, g);
    }
    CP_COMMIT();
}

__global__ __launch_bounds__(256, 1)
void attn_mma(const __nv_bfloat16* __restrict__ qkv_hi,
              const __nv_bfloat16* __restrict__ qkv_lo,
              __nv_bfloat16* __restrict__ out_hi,
              __nv_bfloat16* __restrict__ out_lo)
{
    extern __shared__ char smem[];
    uint32_t sb = smem_u32(smem);
    int tid = threadIdx.x, lane = tid & 31, w = tid >> 5;
    int bh = blockIdx.y;
    int b = bh / NHEAD, h = bh % NHEAD;
    int qb = gridDim.x - 1 - blockIdx.x;   // heavy blocks first
    int qbase = qb * 128;

    size_t planeQ = (size_t)(bh * 3 + 0) * SEQ * HDIM;
    size_t planeK = (size_t)(bh * 3 + 1) * SEQ * HDIM;
    size_t planeV = (size_t)(bh * 3 + 2) * SEQ * HDIM;
    const __nv_bfloat16* qh_g = qkv_hi + planeQ;
    const __nv_bfloat16* ql_g = qkv_lo + planeQ;
    const __nv_bfloat16* kh_g = qkv_hi + planeK;
    const __nv_bfloat16* kl_g = qkv_lo + planeK;
    const __nv_bfloat16* vh_g = qkv_hi + planeV;
    const __nv_bfloat16* vl_g = qkv_lo + planeV;

    // --- Stage Q tile (128x64 hi+lo) through smem stage 0, load A-frags ---
#pragma unroll
    for (int i = 0; i < 8; i++) {
        int idx = tid + i * 256;
        int split = idx >> 10;
        int rem = idx & 1023;
        int row = rem >> 3;
        int ch  = rem & 7;
        const __nv_bfloat16* src = split ? ql_g : qh_g;
        const void* g = src + (size_t)(qbase + row) * HDIM + ch * 8;
        CP_ASYNC16(sb + split * (2 * AT_ARR) + row * AT_PITCH + ch * 16, g);
    }
    CP_COMMIT();
    CP_WAIT0();
    __syncthreads();

    uint32_t qfh[4][4], qfl[4][4];
#pragma unroll
    for (int ds = 0; ds < 4; ds++) {
        uint32_t qa = sb + (w * 16 + (lane & 15)) * AT_PITCH + (lane >> 4) * 16 + ds * 32;
        ldm4(qfh[ds], qa);
        ldm4(qfl[ds], qa + 2 * AT_ARR);
    }
    __syncthreads();

    // --- State ---
    float O[8][4];
#pragma unroll
    for (int dt = 0; dt < 8; dt++)
#pragma unroll
        for (int j = 0; j < 4; j++) O[dt][j] = 0.f;
    float m0 = -1e30f, m1 = -1e30f, L0 = 0.f, L1 = 0.f;

    int r0q = w * 16 + (lane >> 2);      // row (rel) for c0,c1
    int ntile = qbase / 64 + 2;

    attn_issue_kv(sb, 0, kh_g, kl_g, vh_g, vl_g, 0, tid);

    for (int t = 0; t < ntile; t++) {
        if (t + 1 < ntile)
            attn_issue_kv(sb, (t + 1) & 1, kh_g, kl_g, vh_g, vl_g, (t + 1) * 64, tid);
        if (t + 1 < ntile) { CP_WAIT1(); } else { CP_WAIT0(); }
        __syncthreads();

        int kbase = t * 64;
        uint32_t stage = sb + (t & 1) * AT_STAGE;

        // ---- S = Q K^T (split: qh*kh + ql*kh + qh*kl) ----
        float S[8][4];
#pragma unroll
        for (int nt = 0; nt < 8; nt++)
#pragma unroll
            for (int j = 0; j < 4; j++) S[nt][j] = 0.f;

#pragma unroll
        for (int kg = 0; kg < 4; kg++) {
#pragma unroll
            for (int ds = 0; ds < 4; ds++) {
                uint32_t ka = stage + (kg * 16 + (lane & 15)) * AT_PITCH +
                              (lane >> 4) * 16 + ds * 32;
                uint32_t kh4[4], kl4[4];
                ldm4(kh4, ka);
                ldm4(kl4, ka + AT_ARR);
#pragma unroll
                for (int hh = 0; hh < 2; hh++) {
                    int nt = kg * 2 + hh;
                    mma16816(S[nt], qfh[ds], kh4[hh], kh4[hh + 2]);
                    mma16816(S[nt], qfl[ds], kh4[hh], kh4[hh + 2]);
                    mma16816(S[nt], qfh[ds], kl4[hh], kl4[hh + 2]);
                }
            }
        }

        // ---- scale + causal mask ----
        const float scale = 0.125f;
#pragma unroll
        for (int nt = 0; nt < 8; nt++)
#pragma unroll
            for (int j = 0; j < 4; j++) S[nt][j] *= scale;

        if (kbase >= qbase) {
            int row0 = qbase + r0q, row1 = row0 + 8;
#pragma unroll
            for (int nt = 0; nt < 8; nt++) {
                int colb = kbase + nt * 8 + (lane & 3) * 2;
                if (colb > row0)     S[nt][0] = -1e30f;
                if (colb + 1 > row0) S[nt][1] = -1e30f;
                if (colb > row1)     S[nt][2] = -1e30f;
                if (colb + 1 > row1) S[nt][3] = -1e30f;
            }
        }

        // ---- online softmax ----
        float mx0 = -1e30f, mx1 = -1e30f;
#pragma unroll
        for (int nt = 0; nt < 8; nt++) {
            mx0 = fmaxf(mx0, fmaxf(S[nt][0], S[nt][1]));
            mx1 = fmaxf(mx1, fmaxf(S[nt][2], S[nt][3]));
        }
        mx0 = fmaxf(mx0, __shfl_xor_sync(0xffffffffu, mx0, 1));
        mx0 = fmaxf(mx0, __shfl_xor_sync(0xffffffffu, mx0, 2));
        mx1 = fmaxf(mx1, __shfl_xor_sync(0xffffffffu, mx1, 1));
        mx1 = fmaxf(mx1, __shfl_xor_sync(0xffffffffu, mx1, 2));
        float mt0 = fmaxf(m0, mx0), mt1 = fmaxf(m1, mx1);
        float corr0 = __expf(m0 - mt0), corr1 = __expf(m1 - mt1);
        m0 = mt0; m1 = mt1;

        float ls0 = 0.f, ls1 = 0.f;
#pragma unroll
        for (int nt = 0; nt < 8; nt++) {
            S[nt][0] = __expf(S[nt][0] - mt0); ls0 += S[nt][0];
            S[nt][1] = __expf(S[nt][1] - mt0); ls0 += S[nt][1];
            S[nt][2] = __expf(S[nt][2] - mt1); ls1 += S[nt][2];
            S[nt][3] = __expf(S[nt][3] - mt1); ls1 += S[nt][3];
        }
        ls0 += __shfl_xor_sync(0xffffffffu, ls0, 1);
        ls0 += __shfl_xor_sync(0xffffffffu, ls0, 2);
        ls1 += __shfl_xor_sync(0xffffffffu, ls1, 1);
        ls1 += __shfl_xor_sync(0xffffffffu, ls1, 2);
        L0 = L0 * corr0 + ls0;
        L1 = L1 * corr1 + ls1;

#pragma unroll
        for (int dt = 0; dt < 8; dt++) {
            O[dt][0] *= corr0; O[dt][1] *= corr0;
            O[dt][2] *= corr1; O[dt][3] *= corr1;
        }

        // ---- O += P V (split: ph*vh + pl*vh + ph*vl) ----
#pragma unroll
        for (int ks = 0; ks < 4; ks++) {
            uint32_t ap[4], al[4];
            {
                __nv_bfloat16 h0, h1, l0, l1;
                split_bf16(S[2 * ks][0], h0, l0); split_bf16(S[2 * ks][1], h1, l1);
                ap[0] = pack2(h0, h1); al[0] = pack2(l0, l1);
                split_bf16(S[2 * ks][2], h0, l0); split_bf16(S[2 * ks][3], h1, l1);
                ap[1] = pack2(h0, h1); al[1] = pack2(l0, l1);
                split_bf16(S[2 * ks + 1][0], h0, l0); split_bf16(S[2 * ks + 1][1], h1, l1);
                ap[2] = pack2(h0, h1); al[2] = pack2(l0, l1);
                split_bf16(S[2 * ks + 1][2], h0, l0); split_bf16(S[2 * ks + 1][3], h1, l1);
                ap[3] = pack2(h0, h1); al[3] = pack2(l0, l1);
            }
            uint32_t vrow = ks * 16 + (lane & 7) + ((lane >> 4) << 3);
            uint32_t vcol = ((lane >> 3) & 1) * 16;
#pragma unroll
            for (int dg = 0; dg < 4; dg++) {
                uint32_t va = stage + 2 * AT_ARR + vrow * AT_PITCH + vcol + dg * 32;
                uint32_t vh4[4], vl4[4];
                ldm4t(vh4, va);
                ldm4t(vl4, va + AT_ARR);
#pragma unroll
                for (int hh = 0; hh < 2; hh++) {
                    int dt = dg * 2 + hh;
                    mma16816(O[dt], ap, vh4[hh], vh4[hh + 2]);
                    mma16816(O[dt], al, vh4[hh], vh4[hh + 2]);
                    mma16816(O[dt], ap, vl4[hh], vl4[hh + 2]);
                }
            }
        }
        __syncthreads();
    }

    // ---- Epilogue: normalize, split-bf16, write in out-proj A-format ----
    float inv0 = 1.f / L0, inv1 = 1.f / L1;
    int grow0 = b * SEQ + qbase + r0q;
    int grow1 = grow0 + 8;
#pragma unroll
    for (int dt = 0; dt < 8; dt++) {
        int col = h * HDIM + dt * 8 + (lane & 3) * 2;
        float v0 = O[dt][0] * inv0, v1 = O[dt][1] * inv0;
        float v2 = O[dt][2] * inv1, v3 = O[dt][3] * inv1;
        __nv_bfloat16 h0, h1, h2, h3, l0, l1, l2, l3;
        split_bf16(v0, h0, l0); split_bf16(v1, h1, l1);
        split_bf16(v2, h2, l2); split_bf16(v3, h3, l3);
        *(uint32_t*)&out_hi[(size_t)grow0 * EMB + col] = pack2(h0, h1);
        *(uint32_t*)&out_lo[(size_t)grow0 * EMB + col] = pack2(l0, l1);
        *(uint32_t*)&out_hi[(size_t)grow1 * EMB + col] = pack2(h2, h3);
        *(uint32_t*)&out_lo[(size_t)grow1 * EMB + col] = pack2(l2, l3);
    }
}

// ---------------------------------------------------------------------------
extern "C" void kernel_launch(void* const* d_in, const int* in_sizes, int n_in,
                              void* d_out, int out_size)
{
    const float* x     = (const float*)d_in[0];
    const float* Wqkv  = (const float*)d_in[1];
    const float* bqkv  = (const float*)d_in[2];
    const float* Wout  = (const float*)d_in[3];
    const float* bout  = (const float*)d_in[4];
    float* out = (float*)d_out;

    __nv_bfloat16 *xah, *xal, *ath, *atl, *wqh, *wql, *woh, *wol, *qrh, *qrl;
    cudaGetSymbolAddress((void**)&xah, g_xa_hi);
    cudaGetSymbolAddress((void**)&xal, g_xa_lo);
    cudaGetSymbolAddress((void**)&ath, g_at_hi);
    cudaGetSymbolAddress((void**)&atl, g_at_lo);
    cudaGetSymbolAddress((void**)&wqh, g_wq_hi);
    cudaGetSymbolAddress((void**)&wql, g_wq_lo);
    cudaGetSymbolAddress((void**)&woh, g_wo_hi);
    cudaGetSymbolAddress((void**)&wol, g_wo_lo);
    cudaGetSymbolAddress((void**)&qrh, g_qkvr_hi);
    cudaGetSymbolAddress((void**)&qrl, g_qkvr_lo);

    cudaFuncSetAttribute(hmma_gemm_qkv, cudaFuncAttributeMaxDynamicSharedMemorySize, SMEM_B);
    cudaFuncSetAttribute(hmma_gemm_out, cudaFuncAttributeMaxDynamicSharedMemorySize, SMEM_B);
    cudaFuncSetAttribute(attn_mma, cudaFuncAttributeMaxDynamicSharedMemorySize, AT_SMEM);

    // Convert inputs to split-bf16 images
    conv_A<<<(MROWS * 192 + 255) / 256, 256>>>((const float4*)x, xah, xal, MROWS * 192);
    conv_B<<<(768 * (C3 / 4) + 255) / 256, 256>>>((const float4*)Wqkv, wqh, wql, C3);
    conv_B<<<(768 * (EMB / 4) + 255) / 256, 256>>>((const float4*)Wout, woh, wol, EMB);

    // 1) QKV projection -> rearranged split-bf16 [bh][which][T][64]
    {
        dim3 grid(C3 / 128, MROWS / 128);
        hmma_gemm_qkv<<<grid, 256, SMEM_B>>>(xah, xal, wqh, wql, bqkv, qrh, qrl);
    }
    // 2) Tensor-core causal attention -> split-bf16 A-format
    {
        dim3 grid(SEQ / 128, NBH);
        attn_mma<<<grid, 256, AT_SMEM>>>(qrh, qrl, ath, atl);
    }
    // 3) Output projection -> fp32 d_out
    {
        dim3 grid(EMB / 128, MROWS / 128);
        hmma_gemm_out<<<grid, 256, SMEM_B>>>(ath, atl, woh, wol, bout, out, EMB);
    }
}

// round 7
// speedup vs baseline: 3.0329x; 1.1179x over previous
#include <cuda_runtime.h>
#include <cuda_bf16.h>
#include <cstdint>

// Problem constants
#define BATCH 8
#define SEQ   1024
#define EMB   768
#define NHEAD 12
#define HDIM  64
#define C3    (3*EMB)          // 2304
#define MROWS (BATCH*SEQ)      // 8192
#define NKB   24               // 768 / 32 k-blocks
#define NBH   (BATCH*NHEAD)    // 96

// ---------------------------------------------------------------------------
// Scratch (static device arrays)
// ---------------------------------------------------------------------------
__device__ __nv_bfloat16 g_xa_hi[(size_t)MROWS * EMB];
__device__ __nv_bfloat16 g_xa_lo[(size_t)MROWS * EMB];
__device__ __nv_bfloat16 g_at_hi[(size_t)MROWS * EMB];
__device__ __nv_bfloat16 g_at_lo[(size_t)MROWS * EMB];
__device__ __nv_bfloat16 g_wq_hi[(size_t)C3 * EMB];
__device__ __nv_bfloat16 g_wq_lo[(size_t)C3 * EMB];
__device__ __nv_bfloat16 g_wo_hi[(size_t)EMB * EMB];
__device__ __nv_bfloat16 g_wo_lo[(size_t)EMB * EMB];
// QKV rearranged: [(bh*3 + which)][T][64], which: 0=q,1=k,2=v
__device__ __nv_bfloat16 g_qkvr_hi[(size_t)NBH * 3 * SEQ * HDIM];
__device__ __nv_bfloat16 g_qkvr_lo[(size_t)NBH * 3 * SEQ * HDIM];

// ---------------------------------------------------------------------------
// Helpers
// ---------------------------------------------------------------------------
__device__ __forceinline__ uint32_t smem_u32(const void* p) {
    uint32_t a;
    asm("{ .reg .u64 t; cvta.to.shared.u64 t, %1; cvt.u32.u64 %0, t; }"
        : "=r"(a) : "l"(p));
    return a;
}

__device__ __forceinline__ void ldm4(uint32_t* r, uint32_t addr) {
    asm volatile("ldmatrix.sync.aligned.m8n8.x4.shared.b16 {%0,%1,%2,%3}, [%4];"
                 : "=r"(r[0]), "=r"(r[1]), "=r"(r[2]), "=r"(r[3]) : "r"(addr));
}
__device__ __forceinline__ void ldm4t(uint32_t* r, uint32_t addr) {
    asm volatile("ldmatrix.sync.aligned.m8n8.x4.trans.shared.b16 {%0,%1,%2,%3}, [%4];"
                 : "=r"(r[0]), "=r"(r[1]), "=r"(r[2]), "=r"(r[3]) : "r"(addr));
}

__device__ __forceinline__ void mma16816(float* c, const uint32_t* a,
                                         uint32_t b0, uint32_t b1) {
    asm volatile(
        "mma.sync.aligned.m16n8k16.row.col.f32.bf16.bf16.f32 "
        "{%0,%1,%2,%3},{%4,%5,%6,%7},{%8,%9},{%0,%1,%2,%3};"
        : "+f"(c[0]), "+f"(c[1]), "+f"(c[2]), "+f"(c[3])
        : "r"(a[0]), "r"(a[1]), "r"(a[2]), "r"(a[3]), "r"(b0), "r"(b1));
}

#define CP_ASYNC16(dst, src) \
    asm volatile("cp.async.cg.shared.global [%0], [%1], 16;" :: "r"(dst), "l"(src))
#define CP_COMMIT() asm volatile("cp.async.commit_group;" ::: "memory")
#define CP_WAIT1()  asm volatile("cp.async.wait_group 1;" ::: "memory")
#define CP_WAIT0()  asm volatile("cp.async.wait_group 0;" ::: "memory")

__device__ __forceinline__ void split_bf16(float v, __nv_bfloat16& h, __nv_bfloat16& l) {
    h = __float2bfloat16(v);
    l = __float2bfloat16(v - __bfloat162float(h));
}
__device__ __forceinline__ uint32_t pack2(__nv_bfloat16 lo16, __nv_bfloat16 hi16) {
    return ((uint32_t)__bfloat16_as_ushort(hi16) << 16) | __bfloat16_as_ushort(lo16);
}

// ---------------------------------------------------------------------------
// Conversion kernels
// ---------------------------------------------------------------------------
__global__ __launch_bounds__(256)
void conv_A(const float4* __restrict__ in,
            __nv_bfloat16* __restrict__ hi, __nv_bfloat16* __restrict__ lo,
            int total4)
{
    int idx = blockIdx.x * 256 + threadIdx.x;
    if (idx >= total4) return;
    float4 v = in[idx];
    __nv_bfloat16 h0, h1, h2, h3, l0, l1, l2, l3;
    split_bf16(v.x, h0, l0); split_bf16(v.y, h1, l1);
    split_bf16(v.z, h2, l2); split_bf16(v.w, h3, l3);
    uint2 ph, pl;
    ph.x = pack2(h0, h1); ph.y = pack2(h2, h3);
    pl.x = pack2(l0, l1); pl.y = pack2(l2, l3);
    ((uint2*)hi)[idx] = ph;
    ((uint2*)lo)[idx] = pl;
}

// Tiled transpose: W [768][Nout] f32 -> Bimg [Nout][768] bf16 hi/lo.
// 32x32 tiles through smem; coalesced reads and writes.
__global__ __launch_bounds__(256)
void conv_Bt(const float* __restrict__ in,
             __nv_bfloat16* __restrict__ hi, __nv_bfloat16* __restrict__ lo,
             int Nout)
{
    __shared__ float t[32][33];
    int nb = blockIdx.x * 32, kb = blockIdx.y * 32;
    int tx = threadIdx.x & 31, ty = threadIdx.x >> 5;
#pragma unroll
    for (int r = ty; r < 32; r += 8)
        t[r][tx] = in[(size_t)(kb + r) * Nout + nb + tx];
    __syncthreads();
#pragma unroll
    for (int r = ty; r < 32; r += 8) {
        float v = t[tx][r];
        __nv_bfloat16 h, l;
        split_bf16(v, h, l);
        size_t o = (size_t)(nb + r) * EMB + kb + tx;
        hi[o] = h;
        lo[o] = l;
    }
}

// ---------------------------------------------------------------------------
// HMMA split-bf16 GEMM core: 3-stage cp.async pipeline, swizzled pad-free smem,
// single __syncthreads per k-block.
// Smem per stage: 4 arrays (Ah, Al, Bh, Bl), each 128 rows x 64B (32 bf16).
// Chunk swizzle: physical chunk pc = c ^ ((row>>1)&3)  (chunks of 16B).
// ---------------------------------------------------------------------------
#define ARR_S   8192             // 128 * 64
#define STAGE_S 32768            // 4 arrays
#define SMEM_S  (3 * STAGE_S)    // 98304

__device__ __forceinline__ void issue_copy_s(
    uint32_t sb, int stage,
    const __nv_bfloat16* __restrict__ Ah, const __nv_bfloat16* __restrict__ Al,
    const __nv_bfloat16* __restrict__ Bh, const __nv_bfloat16* __restrict__ Bl,
    int mB, int nB, int kb, int tid)
{
    uint32_t dstBase = sb + stage * STAGE_S;
#pragma unroll
    for (int i = 0; i < 8; i++) {
        int idx = tid + i * 256;
        int arr = idx >> 9;          // 0..3
        int rem = idx & 511;
        int row = rem >> 2;          // 0..127
        int c   = rem & 3;           // logical 16B chunk
        int pc  = c ^ ((row >> 1) & 3);
        const __nv_bfloat16* src;
        int rbase;
        if      (arr == 0) { src = Ah; rbase = mB; }
        else if (arr == 1) { src = Al; rbase = mB; }
        else if (arr == 2) { src = Bh; rbase = nB; }
        else               { src = Bl; rbase = nB; }
        const void* g = src + (size_t)(rbase + row) * EMB + kb * 32 + c * 8;
        CP_ASYNC16(dstBase + arr * ARR_S + row * 64 + pc * 16, g);
    }
    CP_COMMIT();
}

__device__ __forceinline__ void gemm_mainloop(
    uint32_t sb, int tid, int lane, int wm, int wn, int mB, int nB,
    const __nv_bfloat16* Ah, const __nv_bfloat16* Al,
    const __nv_bfloat16* Bh, const __nv_bfloat16* Bl,
    float acc[4][4][4])
{
    int lrow = lane & 15;
    int sw   = (lrow >> 1) & 3;
    int chalf = lane >> 4;           // 0/1: k-half within chunk pair

    issue_copy_s(sb, 0, Ah, Al, Bh, Bl, mB, nB, 0, tid);
    issue_copy_s(sb, 1, Ah, Al, Bh, Bl, mB, nB, 1, tid);

    int st = 0;
    for (int kb = 0; kb < NKB; kb++) {
        CP_WAIT1();
        __syncthreads();
        if (kb + 2 < NKB) {
            int s2 = st + 2; if (s2 >= 3) s2 -= 3;
            issue_copy_s(sb, s2, Ah, Al, Bh, Bl, mB, nB, kb + 2, tid);
        } else {
            CP_COMMIT();
        }

        uint32_t base = sb + st * STAGE_S;
        uint32_t aB = base + (wm + lrow) * 64;
        uint32_t bB = base + 2 * ARR_S + (wn + lrow) * 64;

#pragma unroll
        for (int ks = 0; ks < 2; ks++) {
            uint32_t koff = (uint32_t)((chalf + 2 * ks) ^ sw) * 16;
            uint32_t bh[2][4], bl[2][4];
            ldm4(bh[0], bB + koff);
            ldm4(bh[1], bB + 1024 + koff);
            ldm4(bl[0], bB + ARR_S + koff);
            ldm4(bl[1], bB + ARR_S + 1024 + koff);
#pragma unroll
            for (int mt = 0; mt < 4; mt++) {
                uint32_t ah[4], al[4];
                ldm4(ah, aB + mt * 1024 + koff);
                ldm4(al, aB + ARR_S + mt * 1024 + koff);
#pragma unroll
                for (int np = 0; np < 2; np++) {
#pragma unroll
                    for (int h = 0; h < 2; h++) {
                        int nt = np * 2 + h;
                        mma16816(acc[mt][nt], ah, bh[np][h], bh[np][h + 2]);
                        mma16816(acc[mt][nt], al, bh[np][h], bh[np][h + 2]);
                        mma16816(acc[mt][nt], ah, bl[np][h], bl[np][h + 2]);
                    }
                }
            }
        }
        if (++st == 3) st = 0;
    }
}

// Variant 1: QKV projection — epilogue writes split-bf16 rearranged [bh][which][T][64]
__global__ __launch_bounds__(256, 2)
void hmma_gemm_qkv(const __nv_bfloat16* __restrict__ Ah, const __nv_bfloat16* __restrict__ Al,
                   const __nv_bfloat16* __restrict__ Bh, const __nv_bfloat16* __restrict__ Bl,
                   const float* __restrict__ bias,
                   __nv_bfloat16* __restrict__ Ohi, __nv_bfloat16* __restrict__ Olo)
{
    extern __shared__ char smem[];
    uint32_t sb = smem_u32(smem);
    int tid = threadIdx.x, lane = tid & 31, wid = tid >> 5;
    int wm = (wid & 1) * 64, wn = (wid >> 1) * 32;
    int mB = blockIdx.y * 128, nB = blockIdx.x * 128;

    float acc[4][4][4];
#pragma unroll
    for (int a = 0; a < 4; a++)
#pragma unroll
        for (int b = 0; b < 4; b++)
#pragma unroll
            for (int c = 0; c < 4; c++) acc[a][b][c] = 0.f;

    gemm_mainloop(sb, tid, lane, wm, wn, mB, nB, Ah, Al, Bh, Bl, acc);

    int b_ = mB / SEQ;
#pragma unroll
    for (int mt = 0; mt < 4; mt++) {
#pragma unroll
        for (int nt = 0; nt < 4; nt++) {
            int r0 = mB + wm + mt * 16 + (lane >> 2);
            int c0 = nB + wn + nt * 8 + (lane & 3) * 2;
            int which = c0 / EMB;
            int rem = c0 - which * EMB;
            int hh = rem >> 6;
            int d = rem & 63;
            size_t plane = ((size_t)((b_ * NHEAD + hh) * 3 + which)) * SEQ * HDIM;
            float bx = bias[c0], by = bias[c0 + 1];
            float v0 = acc[mt][nt][0] + bx, v1 = acc[mt][nt][1] + by;
            float v2 = acc[mt][nt][2] + bx, v3 = acc[mt][nt][3] + by;
            __nv_bfloat16 h0, h1, h2, h3, l0, l1, l2, l3;
            split_bf16(v0, h0, l0); split_bf16(v1, h1, l1);
            split_bf16(v2, h2, l2); split_bf16(v3, h3, l3);
            int t0 = r0 & (SEQ - 1);
            size_t i0 = plane + (size_t)t0 * HDIM + d;
            size_t i1 = plane + (size_t)(t0 + 8) * HDIM + d;
            *(uint32_t*)&Ohi[i0] = pack2(h0, h1);
            *(uint32_t*)&Olo[i0] = pack2(l0, l1);
            *(uint32_t*)&Ohi[i1] = pack2(h2, h3);
            *(uint32_t*)&Olo[i1] = pack2(l2, l3);
        }
    }
}

// Variant 2: output projection — fp32 epilogue to d_out
__global__ __launch_bounds__(256, 2)
void hmma_gemm_out(const __nv_bfloat16* __restrict__ Ah, const __nv_bfloat16* __restrict__ Al,
                   const __nv_bfloat16* __restrict__ Bh, const __nv_bfloat16* __restrict__ Bl,
                   const float* __restrict__ bias, float* __restrict__ C, int Nout)
{
    extern __shared__ char smem[];
    uint32_t sb = smem_u32(smem);
    int tid = threadIdx.x, lane = tid & 31, wid = tid >> 5;
    int wm = (wid & 1) * 64, wn = (wid >> 1) * 32;
    int mB = blockIdx.y * 128, nB = blockIdx.x * 128;

    float acc[4][4][4];
#pragma unroll
    for (int a = 0; a < 4; a++)
#pragma unroll
        for (int b = 0; b < 4; b++)
#pragma unroll
            for (int c = 0; c < 4; c++) acc[a][b][c] = 0.f;

    gemm_mainloop(sb, tid, lane, wm, wn, mB, nB, Ah, Al, Bh, Bl, acc);

#pragma unroll
    for (int mt = 0; mt < 4; mt++) {
#pragma unroll
        for (int nt = 0; nt < 4; nt++) {
            int r0 = mB + wm + mt * 16 + (lane >> 2);
            int c0 = nB + wn + nt * 8 + (lane & 3) * 2;
            float bx = bias[c0], by = bias[c0 + 1];
            float2 o0, o1;
            o0.x = acc[mt][nt][0] + bx; o0.y = acc[mt][nt][1] + by;
            o1.x = acc[mt][nt][2] + bx; o1.y = acc[mt][nt][3] + by;
            *(float2*)&C[(size_t)r0 * Nout + c0] = o0;
            *(float2*)&C[(size_t)(r0 + 8) * Nout + c0] = o1;
        }
    }
}

// ---------------------------------------------------------------------------
// Tensor-core causal flash attention (split-bf16, mma.sync). Unchanged from R5.
// ---------------------------------------------------------------------------
#define AT_PITCH 144
#define AT_ARR   (64 * AT_PITCH)
#define AT_STAGE (4 * AT_ARR)
#define AT_SMEM  (2 * AT_STAGE)

__device__ __forceinline__ void attn_issue_kv(
    uint32_t sb, int stage,
    const __nv_bfloat16* kh, const __nv_bfloat16* kl,
    const __nv_bfloat16* vh, const __nv_bfloat16* vl,
    int kbase, int tid)
{
    uint32_t dstBase = sb + stage * AT_STAGE;
#pragma unroll
    for (int i = 0; i < 8; i++) {
        int idx = tid + i * 256;
        int arr = idx >> 9;
        int rem = idx & 511;
        int row = rem >> 3;
        int ch  = rem & 7;
        const __nv_bfloat16* src = (arr == 0) ? kh : (arr == 1) ? kl
                                 : (arr == 2) ? vh : vl;
        const void* g = src + (size_t)(kbase + row) * HDIM + ch * 8;
        CP_ASYNC16(dstBase + arr * AT_ARR + row * AT_PITCH + ch * 16, g);
    }
    CP_COMMIT();
}

__global__ __launch_bounds__(256, 1)
void attn_mma(const __nv_bfloat16* __restrict__ qkv_hi,
              const __nv_bfloat16* __restrict__ qkv_lo,
              __nv_bfloat16* __restrict__ out_hi,
              __nv_bfloat16* __restrict__ out_lo)
{
    extern __shared__ char smem[];
    uint32_t sb = smem_u32(smem);
    int tid = threadIdx.x, lane = tid & 31, w = tid >> 5;
    int bh = blockIdx.y;
    int b = bh / NHEAD, h = bh % NHEAD;
    int qb = gridDim.x - 1 - blockIdx.x;
    int qbase = qb * 128;

    size_t planeQ = (size_t)(bh * 3 + 0) * SEQ * HDIM;
    size_t planeK = (size_t)(bh * 3 + 1) * SEQ * HDIM;
    size_t planeV = (size_t)(bh * 3 + 2) * SEQ * HDIM;
    const __nv_bfloat16* qh_g = qkv_hi + planeQ;
    const __nv_bfloat16* ql_g = qkv_lo + planeQ;
    const __nv_bfloat16* kh_g = qkv_hi + planeK;
    const __nv_bfloat16* kl_g = qkv_lo + planeK;
    const __nv_bfloat16* vh_g = qkv_hi + planeV;
    const __nv_bfloat16* vl_g = qkv_lo + planeV;

#pragma unroll
    for (int i = 0; i < 8; i++) {
        int idx = tid + i * 256;
        int split = idx >> 10;
        int rem = idx & 1023;
        int row = rem >> 3;
        int ch  = rem & 7;
        const __nv_bfloat16* src = split ? ql_g : qh_g;
        const void* g = src + (size_t)(qbase + row) * HDIM + ch * 8;
        CP_ASYNC16(sb + split * (2 * AT_ARR) + row * AT_PITCH + ch * 16, g);
    }
    CP_COMMIT();
    CP_WAIT0();
    __syncthreads();

    uint32_t qfh[4][4], qfl[4][4];
#pragma unroll
    for (int ds = 0; ds < 4; ds++) {
        uint32_t qa = sb + (w * 16 + (lane & 15)) * AT_PITCH + (lane >> 4) * 16 + ds * 32;
        ldm4(qfh[ds], qa);
        ldm4(qfl[ds], qa + 2 * AT_ARR);
    }
    __syncthreads();

    float O[8][4];
#pragma unroll
    for (int dt = 0; dt < 8; dt++)
#pragma unroll
        for (int j = 0; j < 4; j++) O[dt][j] = 0.f;
    float m0 = -1e30f, m1 = -1e30f, L0 = 0.f, L1 = 0.f;

    int r0q = w * 16 + (lane >> 2);
    int ntile = qbase / 64 + 2;

    attn_issue_kv(sb, 0, kh_g, kl_g, vh_g, vl_g, 0, tid);

    for (int t = 0; t < ntile; t++) {
        if (t + 1 < ntile)
            attn_issue_kv(sb, (t + 1) & 1, kh_g, kl_g, vh_g, vl_g, (t + 1) * 64, tid);
        if (t + 1 < ntile) { CP_WAIT1(); } else { CP_WAIT0(); }
        __syncthreads();

        int kbase = t * 64;
        uint32_t stage = sb + (t & 1) * AT_STAGE;

        float S[8][4];
#pragma unroll
        for (int nt = 0; nt < 8; nt++)
#pragma unroll
            for (int j = 0; j < 4; j++) S[nt][j] = 0.f;

#pragma unroll
        for (int kg = 0; kg < 4; kg++) {
#pragma unroll
            for (int ds = 0; ds < 4; ds++) {
                uint32_t ka = stage + (kg * 16 + (lane & 15)) * AT_PITCH +
                              (lane >> 4) * 16 + ds * 32;
                uint32_t kh4[4], kl4[4];
                ldm4(kh4, ka);
                ldm4(kl4, ka + AT_ARR);
#pragma unroll
                for (int hh = 0; hh < 2; hh++) {
                    int nt = kg * 2 + hh;
                    mma16816(S[nt], qfh[ds], kh4[hh], kh4[hh + 2]);
                    mma16816(S[nt], qfl[ds], kh4[hh], kh4[hh + 2]);
                    mma16816(S[nt], qfh[ds], kl4[hh], kl4[hh + 2]);
                }
            }
        }

        const float scale = 0.125f;
#pragma unroll
        for (int nt = 0; nt < 8; nt++)
#pragma unroll
            for (int j = 0; j < 4; j++) S[nt][j] *= scale;

        if (kbase >= qbase) {
            int row0 = qbase + r0q, row1 = row0 + 8;
#pragma unroll
            for (int nt = 0; nt < 8; nt++) {
                int colb = kbase + nt * 8 + (lane & 3) * 2;
                if (colb > row0)     S[nt][0] = -1e30f;
                if (colb + 1 > row0) S[nt][1] = -1e30f;
                if (colb > row1)     S[nt][2] = -1e30f;
                if (colb + 1 > row1) S[nt][3] = -1e30f;
            }
        }

        float mx0 = -1e30f, mx1 = -1e30f;
#pragma unroll
        for (int nt = 0; nt < 8; nt++) {
            mx0 = fmaxf(mx0, fmaxf(S[nt][0], S[nt][1]));
            mx1 = fmaxf(mx1, fmaxf(S[nt][2], S[nt][3]));
        }
        mx0 = fmaxf(mx0, __shfl_xor_sync(0xffffffffu, mx0, 1));
        mx0 = fmaxf(mx0, __shfl_xor_sync(0xffffffffu, mx0, 2));
        mx1 = fmaxf(mx1, __shfl_xor_sync(0xffffffffu, mx1, 1));
        mx1 = fmaxf(mx1, __shfl_xor_sync(0xffffffffu, mx1, 2));
        float mt0 = fmaxf(m0, mx0), mt1 = fmaxf(m1, mx1);
        float corr0 = __expf(m0 - mt0), corr1 = __expf(m1 - mt1);
        m0 = mt0; m1 = mt1;

        float ls0 = 0.f, ls1 = 0.f;
#pragma unroll
        for (int nt = 0; nt < 8; nt++) {
            S[nt][0] = __expf(S[nt][0] - mt0); ls0 += S[nt][0];
            S[nt][1] = __expf(S[nt][1] - mt0); ls0 += S[nt][1];
            S[nt][2] = __expf(S[nt][2] - mt1); ls1 += S[nt][2];
            S[nt][3] = __expf(S[nt][3] - mt1); ls1 += S[nt][3];
        }
        ls0 += __shfl_xor_sync(0xffffffffu, ls0, 1);
        ls0 += __shfl_xor_sync(0xffffffffu, ls0, 2);
        ls1 += __shfl_xor_sync(0xffffffffu, ls1, 1);
        ls1 += __shfl_xor_sync(0xffffffffu, ls1, 2);
        L0 = L0 * corr0 + ls0;
        L1 = L1 * corr1 + ls1;

#pragma unroll
        for (int dt = 0; dt < 8; dt++) {
            O[dt][0] *= corr0; O[dt][1] *= corr0;
            O[dt][2] *= corr1; O[dt][3] *= corr1;
        }

#pragma unroll
        for (int ks = 0; ks < 4; ks++) {
            uint32_t ap[4], al[4];
            {
                __nv_bfloat16 h0, h1, l0, l1;
                split_bf16(S[2 * ks][0], h0, l0); split_bf16(S[2 * ks][1], h1, l1);
                ap[0] = pack2(h0, h1); al[0] = pack2(l0, l1);
                split_bf16(S[2 * ks][2], h0, l0); split_bf16(S[2 * ks][3], h1, l1);
                ap[1] = pack2(h0, h1); al[1] = pack2(l0, l1);
                split_bf16(S[2 * ks + 1][0], h0, l0); split_bf16(S[2 * ks + 1][1], h1, l1);
                ap[2] = pack2(h0, h1); al[2] = pack2(l0, l1);
                split_bf16(S[2 * ks + 1][2], h0, l0); split_bf16(S[2 * ks + 1][3], h1, l1);
                ap[3] = pack2(h0, h1); al[3] = pack2(l0, l1);
            }
            uint32_t vrow = ks * 16 + (lane & 7) + ((lane >> 4) << 3);
            uint32_t vcol = ((lane >> 3) & 1) * 16;
#pragma unroll
            for (int dg = 0; dg < 4; dg++) {
                uint32_t va = stage + 2 * AT_ARR + vrow * AT_PITCH + vcol + dg * 32;
                uint32_t vh4[4], vl4[4];
                ldm4t(vh4, va);
                ldm4t(vl4, va + AT_ARR);
#pragma unroll
                for (int hh = 0; hh < 2; hh++) {
                    int dt = dg * 2 + hh;
                    mma16816(O[dt], ap, vh4[hh], vh4[hh + 2]);
                    mma16816(O[dt], al, vh4[hh], vh4[hh + 2]);
                    mma16816(O[dt], ap, vl4[hh], vl4[hh + 2]);
                }
            }
        }
        __syncthreads();
    }

    float inv0 = 1.f / L0, inv1 = 1.f / L1;
    int grow0 = b * SEQ + qbase + r0q;
    int grow1 = grow0 + 8;
#pragma unroll
    for (int dt = 0; dt < 8; dt++) {
        int col = h * HDIM + dt * 8 + (lane & 3) * 2;
        float v0 = O[dt][0] * inv0, v1 = O[dt][1] * inv0;
        float v2 = O[dt][2] * inv1, v3 = O[dt][3] * inv1;
        __nv_bfloat16 h0, h1, h2, h3, l0, l1, l2, l3;
        split_bf16(v0, h0, l0); split_bf16(v1, h1, l1);
        split_bf16(v2, h2, l2); split_bf16(v3, h3, l3);
        *(uint32_t*)&out_hi[(size_t)grow0 * EMB + col] = pack2(h0, h1);
        *(uint32_t*)&out_lo[(size_t)grow0 * EMB + col] = pack2(l0, l1);
        *(uint32_t*)&out_hi[(size_t)grow1 * EMB + col] = pack2(h2, h3);
        *(uint32_t*)&out_lo[(size_t)grow1 * EMB + col] = pack2(l2, l3);
    }
}

// ---------------------------------------------------------------------------
extern "C" void kernel_launch(void* const* d_in, const int* in_sizes, int n_in,
                              void* d_out, int out_size)
{
    const float* x     = (const float*)d_in[0];
    const float* Wqkv  = (const float*)d_in[1];
    const float* bqkv  = (const float*)d_in[2];
    const float* Wout  = (const float*)d_in[3];
    const float* bout  = (const float*)d_in[4];
    float* out = (float*)d_out;

    __nv_bfloat16 *xah, *xal, *ath, *atl, *wqh, *wql, *woh, *wol, *qrh, *qrl;
    cudaGetSymbolAddress((void**)&xah, g_xa_hi);
    cudaGetSymbolAddress((void**)&xal, g_xa_lo);
    cudaGetSymbolAddress((void**)&ath, g_at_hi);
    cudaGetSymbolAddress((void**)&atl, g_at_lo);
    cudaGetSymbolAddress((void**)&wqh, g_wq_hi);
    cudaGetSymbolAddress((void**)&wql, g_wq_lo);
    cudaGetSymbolAddress((void**)&woh, g_wo_hi);
    cudaGetSymbolAddress((void**)&wol, g_wo_lo);
    cudaGetSymbolAddress((void**)&qrh, g_qkvr_hi);
    cudaGetSymbolAddress((void**)&qrl, g_qkvr_lo);

    cudaFuncSetAttribute(hmma_gemm_qkv, cudaFuncAttributeMaxDynamicSharedMemorySize, SMEM_S);
    cudaFuncSetAttribute(hmma_gemm_out, cudaFuncAttributeMaxDynamicSharedMemorySize, SMEM_S);
    cudaFuncSetAttribute(attn_mma, cudaFuncAttributeMaxDynamicSharedMemorySize, AT_SMEM);

    // Convert inputs to split-bf16 images
    conv_A<<<(MROWS * 192 + 255) / 256, 256>>>((const float4*)x, xah, xal, MROWS * 192);
    {
        dim3 g1(C3 / 32, 768 / 32);
        conv_Bt<<<g1, 256>>>(Wqkv, wqh, wql, C3);
        dim3 g2(EMB / 32, 768 / 32);
        conv_Bt<<<g2, 256>>>(Wout, woh, wol, EMB);
    }

    // 1) QKV projection -> rearranged split-bf16 [bh][which][T][64]
    {
        dim3 grid(C3 / 128, MROWS / 128);
        hmma_gemm_qkv<<<grid, 256, SMEM_S>>>(xah, xal, wqh, wql, bqkv, qrh, qrl);
    }
    // 2) Tensor-core causal attention -> split-bf16 A-format
    {
        dim3 grid(SEQ / 128, NBH);
        attn_mma<<<grid, 256, AT_SMEM>>>(qrh, qrl, ath, atl);
    }
    // 3) Output projection -> fp32 d_out
    {
        dim3 grid(EMB / 128, MROWS / 128);
        hmma_gemm_out<<<grid, 256, SMEM_S>>>(ath, atl, woh, wol, bout, out, EMB);
    }
}